// round 6
// baseline (speedup 1.0000x reference)
#include <cuda_runtime.h>
#include <math.h>

// Shapes (fixed by the problem)
//  x       [16][16][4096]
//  conv_w  [256][16][9]
//  conv_b  [256]
//  caps_w  [8][16][256]
//  caps_b  [8][16]
//  W       [8][16][16]
//  out     [8][16][8][4096]  (n0, k, n, s)
//
// Algebra:
//  s0[n0,k,n,s] = Weff[n,k] (*) xc[n0,k] + beff           (xc = Σ_b C[n0,k,b]·x[b], ΣC=1)
//  U[k,n,s]     = Weff[n,k] (*) xU + 16·beff              (xU = Σ_b x[b])
//  s1 = s0·(1 + f0·s0·U); s2 = s0 + f1·s1²·U; out = f2·s2; f(SS)=√SS/(1+SS), SS=Σ_s s²

__device__ float g_C[128 * 16];          // [n0*16+k][b]
__device__ float g_Weff[128 * 144];      // [n*16+k][ic*9+dk]
__device__ float g_beff[128];            // [n*16+k]
__device__ float g_xc[128 * 16 * 4096];  // [n0*16+k][ic][s]   (32 MB)
__device__ float g_xU[16 * 4096];        // [ic][s]
__device__ float g_U[128 * 4096];        // [k*8+n][s]          (2 MB)
__device__ float g_s0[1024 * 4096];      // [n0*128+k*8+n][s]   (16 MB)

// ---------------------------------------------------------------------------
// K0: softmax rows of W (over b axis) and effective bias
// ---------------------------------------------------------------------------
__global__ void k_setup(const float* __restrict__ Wr,
                        const float* __restrict__ caps_w,
                        const float* __restrict__ conv_b,
                        const float* __restrict__ caps_b) {
    int t = threadIdx.x;
    if (t < 128) {
        int n0 = t >> 4, k = t & 15;
        float m = -1e30f;
        float e[16];
        #pragma unroll
        for (int b = 0; b < 16; b++)
            m = fmaxf(m, Wr[(n0 * 16 + b) * 16 + k]);
        float sum = 0.f;
        #pragma unroll
        for (int b = 0; b < 16; b++) {
            float v = expf(Wr[(n0 * 16 + b) * 16 + k] - m);
            e[b] = v;
            sum += v;
        }
        float inv = 1.f / sum;
        #pragma unroll
        for (int b = 0; b < 16; b++)
            g_C[(n0 * 16 + k) * 16 + b] = e[b] * inv;

        float acc = caps_b[t];
        for (int oc = 0; oc < 256; oc++)
            acc += caps_w[t * 256 + oc] * conv_b[oc];
        g_beff[t] = acc;
    }
}

// ---------------------------------------------------------------------------
// K0b: Weff[nk][ic*9+dk] = sum_oc caps_w[nk][oc] * conv_w[oc][ic][dk]
// ---------------------------------------------------------------------------
__global__ void k_weff(const float* __restrict__ caps_w,
                       const float* __restrict__ conv_w) {
    int nk = blockIdx.x;
    __shared__ float cw[256];
    for (int i = threadIdx.x; i < 256; i += blockDim.x)
        cw[i] = caps_w[nk * 256 + i];
    __syncthreads();
    int t = threadIdx.x;
    if (t < 144) {
        int ic = t / 9, dk = t - ic * 9;
        float acc = 0.f;
        for (int oc = 0; oc < 256; oc++)
            acc += cw[oc] * conv_w[(oc * 16 + ic) * 9 + dk];
        g_Weff[nk * 144 + t] = acc;
    }
}

// ---------------------------------------------------------------------------
// K1: xc[n0k][ic][s] = sum_b C[n0k][b] * x[b][ic][s];  xU[ic][s] = sum_b x
// grid (ic=16, stile=8 of 512, nkchunk=4 of 32); 128 threads, 4 s per thread
// ---------------------------------------------------------------------------
__global__ __launch_bounds__(128) void k_xc(const float* __restrict__ x) {
    const int ic = blockIdx.x;
    const int sbase = blockIdx.y * 512;
    const int nk0 = blockIdx.z * 32;
    const int tid = threadIdx.x;

    __shared__ __align__(16) float xs[16][512];
    __shared__ float Cs[32][16];

    for (int idx = tid; idx < 16 * 128; idx += 128) {
        int b = idx >> 7, q = idx & 127;
        float4 v = *reinterpret_cast<const float4*>(&x[(b * 16 + ic) * 4096 + sbase + q * 4]);
        *reinterpret_cast<float4*>(&xs[b][q * 4]) = v;
    }
    for (int idx = tid; idx < 32 * 16; idx += 128)
        Cs[idx >> 4][idx & 15] = g_C[nk0 * 16 + idx];
    __syncthreads();

    float xb[16][4];
    #pragma unroll
    for (int b = 0; b < 16; b++) {
        float4 v = *reinterpret_cast<const float4*>(&xs[b][tid * 4]);
        xb[b][0] = v.x; xb[b][1] = v.y; xb[b][2] = v.z; xb[b][3] = v.w;
    }

    if (nk0 == 0) {  // xU once
        float u0 = 0.f, u1 = 0.f, u2 = 0.f, u3 = 0.f;
        #pragma unroll
        for (int b = 0; b < 16; b++) {
            u0 += xb[b][0]; u1 += xb[b][1]; u2 += xb[b][2]; u3 += xb[b][3];
        }
        *reinterpret_cast<float4*>(&g_xU[ic * 4096 + sbase + tid * 4]) =
            make_float4(u0, u1, u2, u3);
    }

    for (int j = 0; j < 32; j++) {
        float a0 = 0.f, a1 = 0.f, a2 = 0.f, a3 = 0.f;
        #pragma unroll
        for (int b = 0; b < 16; b++) {
            float c = Cs[j][b];
            a0 = fmaf(c, xb[b][0], a0);
            a1 = fmaf(c, xb[b][1], a1);
            a2 = fmaf(c, xb[b][2], a2);
            a3 = fmaf(c, xb[b][3], a3);
        }
        *reinterpret_cast<float4*>(&g_xc[((nk0 + j) * 16 + ic) * 4096 + sbase + tid * 4]) =
            make_float4(a0, a1, a2, a3);
    }
}

// ---------------------------------------------------------------------------
// shared conv body: acc[8]+xv[16]+w[144] -> 168 regs, no spill (proven shape)
// block 128 thr: n = tid&7, g = tid>>3 (0..15); c-loop 2x over 128-s halves
// ---------------------------------------------------------------------------
__device__ __forceinline__ void conv_tile(const float (*xt)[264], const float* w,
                                          float bv, float* orow, int g) {
    #pragma unroll
    for (int c = 0; c < 2; c++) {
        const int sb = c * 128 + g * 8;
        float acc[8];
        #pragma unroll
        for (int t = 0; t < 8; t++) acc[t] = bv;

        #pragma unroll
        for (int ic = 0; ic < 16; ic++) {
            float xv[16];
            #pragma unroll
            for (int q = 0; q < 4; q++) {
                float4 v = *reinterpret_cast<const float4*>(&xt[ic][sb + q * 4]);
                xv[q * 4 + 0] = v.x; xv[q * 4 + 1] = v.y;
                xv[q * 4 + 2] = v.z; xv[q * 4 + 3] = v.w;
            }
            #pragma unroll
            for (int dk = 0; dk < 9; dk++) {
                float wv = w[ic * 9 + dk];
                #pragma unroll
                for (int t = 0; t < 8; t++)
                    acc[t] = fmaf(wv, xv[t + dk], acc[t]);
            }
        }
        *reinterpret_cast<float4*>(&orow[sb])     = make_float4(acc[0], acc[1], acc[2], acc[3]);
        *reinterpret_cast<float4*>(&orow[sb + 4]) = make_float4(acc[4], acc[5], acc[6], acc[7]);
    }
}

// ---------------------------------------------------------------------------
// K2: U[k*8+n][s] = Weff[n*16+k] (*) xU + 16*beff.  grid (stile16, k16), 128 thr
// ---------------------------------------------------------------------------
__global__ __launch_bounds__(128) void k_ucalc() {
    const int sc = blockIdx.x * 256;
    const int k  = blockIdx.y;
    const int tid = threadIdx.x;
    const int n = tid & 7;
    const int g = tid >> 3;
    const int nk = n * 16 + k;

    __shared__ __align__(16) float xt[16][264];

    for (int j = tid; j < 16 * 264; j += 128) {
        int ic = j / 264, jj = j - ic * 264;
        int s = sc - 4 + jj;
        xt[ic][jj] = (s >= 0 && s < 4096) ? g_xU[ic * 4096 + s] : 0.f;
    }

    float w[144];
    #pragma unroll
    for (int i = 0; i < 144; i++) w[i] = g_Weff[nk * 144 + i];
    const float bv = 16.f * g_beff[nk];
    __syncthreads();

    conv_tile(xt, w, bv, &g_U[(k * 8 + n) * 4096 + sc], g);
}

// ---------------------------------------------------------------------------
// K3: s0[n0,k,n][s] = Weff[n*16+k] (*) xc[n0*16+k] + beff
// grid (stile16, n0k128), 128 thr
// ---------------------------------------------------------------------------
__global__ __launch_bounds__(128) void k_s0conv() {
    const int sc = blockIdx.x * 256;
    const int n0k = blockIdx.y;            // n0*16 + k
    const int k = n0k & 15;
    const int tid = threadIdx.x;
    const int n = tid & 7;
    const int g = tid >> 3;
    const int nk = n * 16 + k;

    __shared__ __align__(16) float xt[16][264];

    for (int j = tid; j < 16 * 264; j += 128) {
        int ic = j / 264, jj = j - ic * 264;
        int s = sc - 4 + jj;
        xt[ic][jj] = (s >= 0 && s < 4096) ? g_xc[(n0k * 16 + ic) * 4096 + s] : 0.f;
    }

    float w[144];
    #pragma unroll
    for (int i = 0; i < 144; i++) w[i] = g_Weff[nk * 144 + i];
    const float bv = g_beff[nk];
    __syncthreads();

    conv_tile(xt, w, bv,
              &g_s0[(((n0k >> 4) * 128) + k * 8 + n) * 4096 + sc], g);
}

// ---------------------------------------------------------------------------
// K4: squash iterations. one block per (n0,k,n) = bid; reads s0 row + U row.
// ---------------------------------------------------------------------------
__device__ __forceinline__ float block_reduce(float p, float* red, int tid) {
    #pragma unroll
    for (int o = 16; o > 0; o >>= 1)
        p += __shfl_xor_sync(0xffffffffu, p, o);
    __syncthreads();
    if ((tid & 31) == 0) red[tid >> 5] = p;
    __syncthreads();
    if (tid == 0) {
        float s = 0.f;
        #pragma unroll
        for (int i = 0; i < 8; i++) s += red[i];
        red[8] = s;
    }
    __syncthreads();
    return red[8];
}

__global__ __launch_bounds__(256) void k_squash(float* __restrict__ out) {
    const int bid = blockIdx.x;            // n0*128 + k*8 + n
    const int kn2 = bid & 127;             // k*8+n
    const int tid = threadIdx.x;

    __shared__ __align__(16) float s0s[4096];
    __shared__ __align__(16) float Us[4096];
    __shared__ float red[9];

    const float4* s0g = reinterpret_cast<const float4*>(&g_s0[bid * 4096]);
    const float4* Ug  = reinterpret_cast<const float4*>(&g_U[kn2 * 4096]);
    for (int i = tid; i < 1024; i += 256) {
        *reinterpret_cast<float4*>(&s0s[i * 4]) = s0g[i];
        *reinterpret_cast<float4*>(&Us[i * 4])  = Ug[i];
    }
    __syncthreads();

    float p, SS;

    p = 0.f;
    for (int s = tid; s < 4096; s += 256) { float v = s0s[s]; p = fmaf(v, v, p); }
    SS = block_reduce(p, red, tid);
    const float f0 = sqrtf(SS) / (1.f + SS);

    p = 0.f;
    for (int s = tid; s < 4096; s += 256) {
        float a = s0s[s], Uv = Us[s];
        float s1 = a * (1.f + f0 * a * Uv);
        p = fmaf(s1, s1, p);
    }
    SS = block_reduce(p, red, tid);
    const float f1 = sqrtf(SS) / (1.f + SS);

    p = 0.f;
    for (int s = tid; s < 4096; s += 256) {
        float a = s0s[s], Uv = Us[s];
        float s1 = a * (1.f + f0 * a * Uv);
        float s2 = a + f1 * s1 * s1 * Uv;
        p = fmaf(s2, s2, p);
    }
    SS = block_reduce(p, red, tid);
    const float f2 = sqrtf(SS) / (1.f + SS);

    float* orow = out + bid * 4096;
    for (int s = tid; s < 4096; s += 256) {
        float a = s0s[s], Uv = Us[s];
        float s1 = a * (1.f + f0 * a * Uv);
        float s2 = a + f1 * s1 * s1 * Uv;
        orow[s] = f2 * s2;
    }
}

// ---------------------------------------------------------------------------
extern "C" void kernel_launch(void* const* d_in, const int* in_sizes, int n_in,
                              void* d_out, int out_size) {
    const float* x      = (const float*)d_in[0];
    const float* conv_w = (const float*)d_in[1];
    const float* conv_b = (const float*)d_in[2];
    const float* caps_w = (const float*)d_in[3];
    const float* caps_b = (const float*)d_in[4];
    const float* W      = (const float*)d_in[5];
    float* out = (float*)d_out;

    k_setup<<<1, 128>>>(W, caps_w, conv_b, caps_b);
    k_weff<<<128, 160>>>(caps_w, conv_w);
    k_xc<<<dim3(16, 8, 4), 128>>>(x);
    k_ucalc<<<dim3(16, 16), 128>>>();
    k_s0conv<<<dim3(16, 128), 128>>>();
    k_squash<<<1024, 256>>>(out);
}

// round 7
// speedup vs baseline: 2.0045x; 2.0045x over previous
#include <cuda_runtime.h>
#include <math.h>

// Shapes (fixed by the problem)
//  x       [16][16][4096]
//  conv_w  [256][16][9]
//  conv_b  [256]
//  caps_w  [8][16][256]
//  caps_b  [8][16]
//  W       [8][16][16]
//  out     [8][16][8][4096]  (n0, k, n, s)
//
// Algebra:
//  s0[n0,k,n,s] = Weff[n,k] (*) xc[n0,k] + beff           (xc = Σ_b C[n0,k,b]·x[b], ΣC=1)
//  U[k,n,s]     = Weff[n,k] (*) xU + 16·beff              (xU = Σ_b x[b])
//  s1 = s0·(1 + f0·s0·U); s2 = s0 + f1·s1²·U; out = f2·s2; f(SS)=√SS/(1+SS), SS=Σ_s s²

__device__ float g_C[128 * 16];          // [n0*16+k][b]
__device__ float g_Weff[128 * 144];      // [n*16+k][ic*9+dk]
__device__ float g_beff[128];            // [n*16+k]
__device__ float g_xc[128 * 16 * 4096];  // [n0*16+k][ic][s]   (32 MB)
__device__ float g_xU[16 * 4096];        // [ic][s]
__device__ float g_U[128 * 4096];        // [k*8+n][s]          (2 MB)
__device__ float g_s0[1024 * 4096];      // [n0*128+k*8+n][s]   (16 MB)

// ---------------------------------------------------------------------------
// K0: softmax rows of W (over b axis) and effective bias
// ---------------------------------------------------------------------------
__global__ void k_setup(const float* __restrict__ Wr,
                        const float* __restrict__ caps_w,
                        const float* __restrict__ conv_b,
                        const float* __restrict__ caps_b) {
    int t = threadIdx.x;
    if (t < 128) {
        int n0 = t >> 4, k = t & 15;
        float m = -1e30f;
        float e[16];
        #pragma unroll
        for (int b = 0; b < 16; b++)
            m = fmaxf(m, Wr[(n0 * 16 + b) * 16 + k]);
        float sum = 0.f;
        #pragma unroll
        for (int b = 0; b < 16; b++) {
            float v = expf(Wr[(n0 * 16 + b) * 16 + k] - m);
            e[b] = v;
            sum += v;
        }
        float inv = 1.f / sum;
        #pragma unroll
        for (int b = 0; b < 16; b++)
            g_C[(n0 * 16 + k) * 16 + b] = e[b] * inv;

        float acc = caps_b[t];
        for (int oc = 0; oc < 256; oc++)
            acc += caps_w[t * 256 + oc] * conv_b[oc];
        g_beff[t] = acc;
    }
}

// ---------------------------------------------------------------------------
// K0b: Weff[nk][ic*9+dk] = sum_oc caps_w[nk][oc] * conv_w[oc][ic][dk]
// ---------------------------------------------------------------------------
__global__ void k_weff(const float* __restrict__ caps_w,
                       const float* __restrict__ conv_w) {
    int nk = blockIdx.x;
    __shared__ float cw[256];
    for (int i = threadIdx.x; i < 256; i += blockDim.x)
        cw[i] = caps_w[nk * 256 + i];
    __syncthreads();
    int t = threadIdx.x;
    if (t < 144) {
        int ic = t / 9, dk = t - ic * 9;
        float acc = 0.f;
        for (int oc = 0; oc < 256; oc++)
            acc += cw[oc] * conv_w[(oc * 16 + ic) * 9 + dk];
        g_Weff[nk * 144 + t] = acc;
    }
}

// ---------------------------------------------------------------------------
// K1: xc[n0k][ic][s] = sum_b C[n0k][b] * x[b][ic][s];  xU[ic][s] = sum_b x
// grid (ic=16, stile=8 of 512, nkchunk=4 of 32); 128 threads, 4 s per thread
// ---------------------------------------------------------------------------
__global__ __launch_bounds__(128) void k_xc(const float* __restrict__ x) {
    const int ic = blockIdx.x;
    const int sbase = blockIdx.y * 512;
    const int nk0 = blockIdx.z * 32;
    const int tid = threadIdx.x;

    __shared__ __align__(16) float xs[16][512];
    __shared__ float Cs[32][16];

    for (int idx = tid; idx < 16 * 128; idx += 128) {
        int b = idx >> 7, q = idx & 127;
        float4 v = *reinterpret_cast<const float4*>(&x[(b * 16 + ic) * 4096 + sbase + q * 4]);
        *reinterpret_cast<float4*>(&xs[b][q * 4]) = v;
    }
    for (int idx = tid; idx < 32 * 16; idx += 128)
        Cs[idx >> 4][idx & 15] = g_C[nk0 * 16 + idx];
    __syncthreads();

    float xb[16][4];
    #pragma unroll
    for (int b = 0; b < 16; b++) {
        float4 v = *reinterpret_cast<const float4*>(&xs[b][tid * 4]);
        xb[b][0] = v.x; xb[b][1] = v.y; xb[b][2] = v.z; xb[b][3] = v.w;
    }

    if (nk0 == 0) {  // xU once
        float u0 = 0.f, u1 = 0.f, u2 = 0.f, u3 = 0.f;
        #pragma unroll
        for (int b = 0; b < 16; b++) {
            u0 += xb[b][0]; u1 += xb[b][1]; u2 += xb[b][2]; u3 += xb[b][3];
        }
        *reinterpret_cast<float4*>(&g_xU[ic * 4096 + sbase + tid * 4]) =
            make_float4(u0, u1, u2, u3);
    }

    for (int j = 0; j < 32; j++) {
        float a0 = 0.f, a1 = 0.f, a2 = 0.f, a3 = 0.f;
        #pragma unroll
        for (int b = 0; b < 16; b++) {
            float c = Cs[j][b];
            a0 = fmaf(c, xb[b][0], a0);
            a1 = fmaf(c, xb[b][1], a1);
            a2 = fmaf(c, xb[b][2], a2);
            a3 = fmaf(c, xb[b][3], a3);
        }
        *reinterpret_cast<float4*>(&g_xc[((nk0 + j) * 16 + ic) * 4096 + sbase + tid * 4]) =
            make_float4(a0, a1, a2, a3);
    }
}

// ---------------------------------------------------------------------------
// shared conv body: weights in SMEM (ws, row stride 148 -> conflict-free for
// the 8 n-lanes of a warp), per-ic 9-reg weight staging, acc[16]+xv[24].
// block 128 thr: n = tid&7, g = tid>>3 (0..15); 16 outputs per thread.
// ---------------------------------------------------------------------------
#define WS_STRIDE 148

__device__ __forceinline__ void conv_body(const float (*xt)[264],
                                          const float* ws_row,
                                          float bv, float* orow, int g) {
    float acc[16];
    #pragma unroll
    for (int t = 0; t < 16; t++) acc[t] = bv;
    const int sb = g * 16;

    #pragma unroll
    for (int ic = 0; ic < 16; ic++) {
        float xv[24];
        #pragma unroll
        for (int q = 0; q < 6; q++) {
            float4 v = *reinterpret_cast<const float4*>(&xt[ic][sb + q * 4]);
            xv[q * 4 + 0] = v.x; xv[q * 4 + 1] = v.y;
            xv[q * 4 + 2] = v.z; xv[q * 4 + 3] = v.w;
        }
        float wr[9];
        #pragma unroll
        for (int d = 0; d < 9; d++) wr[d] = ws_row[ic * 9 + d];
        #pragma unroll
        for (int dk = 0; dk < 9; dk++) {
            #pragma unroll
            for (int t = 0; t < 16; t++)
                acc[t] = fmaf(wr[dk], xv[t + dk], acc[t]);
        }
    }

    #pragma unroll
    for (int q = 0; q < 4; q++)
        *reinterpret_cast<float4*>(&orow[sb + q * 4]) =
            make_float4(acc[q * 4], acc[q * 4 + 1], acc[q * 4 + 2], acc[q * 4 + 3]);
}

// ---------------------------------------------------------------------------
// K2: U[k*8+n][s] = Weff[n*16+k] (*) xU + 16*beff.  grid (stile16, k16)
// ---------------------------------------------------------------------------
__global__ __launch_bounds__(128) void k_ucalc() {
    const int sc = blockIdx.x * 256;
    const int k  = blockIdx.y;
    const int tid = threadIdx.x;
    const int n = tid & 7;
    const int g = tid >> 3;

    __shared__ __align__(16) float xt[16][264];
    __shared__ float ws[8 * WS_STRIDE];
    __shared__ float bs[8];

    for (int j = tid; j < 16 * 264; j += 128) {
        int ic = j / 264, jj = j - ic * 264;
        int s = sc - 4 + jj;
        xt[ic][jj] = (s >= 0 && s < 4096) ? g_xU[ic * 4096 + s] : 0.f;
    }
    for (int i = tid; i < 8 * 144; i += 128) {
        int n2 = i / 144, j = i - n2 * 144;
        ws[n2 * WS_STRIDE + j] = g_Weff[(n2 * 16 + k) * 144 + j];
    }
    if (tid < 8) bs[tid] = 16.f * g_beff[tid * 16 + k];
    __syncthreads();

    conv_body(xt, ws + n * WS_STRIDE, bs[n], &g_U[(k * 8 + n) * 4096 + sc], g);
}

// ---------------------------------------------------------------------------
// K3: s0[n0,k,n][s] = Weff[n*16+k] (*) xc[n0*16+k] + beff
// grid (stile16, n0k128)
// ---------------------------------------------------------------------------
__global__ __launch_bounds__(128) void k_s0conv() {
    const int sc = blockIdx.x * 256;
    const int n0k = blockIdx.y;            // n0*16 + k
    const int k = n0k & 15;
    const int tid = threadIdx.x;
    const int n = tid & 7;
    const int g = tid >> 3;

    __shared__ __align__(16) float xt[16][264];
    __shared__ float ws[8 * WS_STRIDE];
    __shared__ float bs[8];

    for (int j = tid; j < 16 * 264; j += 128) {
        int ic = j / 264, jj = j - ic * 264;
        int s = sc - 4 + jj;
        xt[ic][jj] = (s >= 0 && s < 4096) ? g_xc[(n0k * 16 + ic) * 4096 + s] : 0.f;
    }
    for (int i = tid; i < 8 * 144; i += 128) {
        int n2 = i / 144, j = i - n2 * 144;
        ws[n2 * WS_STRIDE + j] = g_Weff[(n2 * 16 + k) * 144 + j];
    }
    if (tid < 8) bs[tid] = g_beff[tid * 16 + k];
    __syncthreads();

    conv_body(xt, ws + n * WS_STRIDE, bs[n],
              &g_s0[(((n0k >> 4) * 128) + k * 8 + n) * 4096 + sc], g);
}

// ---------------------------------------------------------------------------
// K4: squash iterations. one block per (n0,k,n) = bid; reads s0 row + U row.
// ---------------------------------------------------------------------------
__device__ __forceinline__ float block_reduce(float p, float* red, int tid) {
    #pragma unroll
    for (int o = 16; o > 0; o >>= 1)
        p += __shfl_xor_sync(0xffffffffu, p, o);
    __syncthreads();
    if ((tid & 31) == 0) red[tid >> 5] = p;
    __syncthreads();
    if (tid == 0) {
        float s = 0.f;
        #pragma unroll
        for (int i = 0; i < 8; i++) s += red[i];
        red[8] = s;
    }
    __syncthreads();
    return red[8];
}

__global__ __launch_bounds__(256) void k_squash(float* __restrict__ out) {
    const int bid = blockIdx.x;            // n0*128 + k*8 + n
    const int kn2 = bid & 127;             // k*8+n
    const int tid = threadIdx.x;

    __shared__ __align__(16) float s0s[4096];
    __shared__ __align__(16) float Us[4096];
    __shared__ float red[9];

    const float4* s0g = reinterpret_cast<const float4*>(&g_s0[bid * 4096]);
    const float4* Ug  = reinterpret_cast<const float4*>(&g_U[kn2 * 4096]);
    for (int i = tid; i < 1024; i += 256) {
        *reinterpret_cast<float4*>(&s0s[i * 4]) = s0g[i];
        *reinterpret_cast<float4*>(&Us[i * 4])  = Ug[i];
    }
    __syncthreads();

    float p, SS;

    p = 0.f;
    for (int s = tid; s < 4096; s += 256) { float v = s0s[s]; p = fmaf(v, v, p); }
    SS = block_reduce(p, red, tid);
    const float f0 = sqrtf(SS) / (1.f + SS);

    p = 0.f;
    for (int s = tid; s < 4096; s += 256) {
        float a = s0s[s], Uv = Us[s];
        float s1 = a * (1.f + f0 * a * Uv);
        p = fmaf(s1, s1, p);
    }
    SS = block_reduce(p, red, tid);
    const float f1 = sqrtf(SS) / (1.f + SS);

    p = 0.f;
    for (int s = tid; s < 4096; s += 256) {
        float a = s0s[s], Uv = Us[s];
        float s1 = a * (1.f + f0 * a * Uv);
        float s2 = a + f1 * s1 * s1 * Uv;
        p = fmaf(s2, s2, p);
    }
    SS = block_reduce(p, red, tid);
    const float f2 = sqrtf(SS) / (1.f + SS);

    float* orow = out + bid * 4096;
    for (int s = tid; s < 4096; s += 256) {
        float a = s0s[s], Uv = Us[s];
        float s1 = a * (1.f + f0 * a * Uv);
        float s2 = a + f1 * s1 * s1 * Uv;
        orow[s] = f2 * s2;
    }
}

// ---------------------------------------------------------------------------
extern "C" void kernel_launch(void* const* d_in, const int* in_sizes, int n_in,
                              void* d_out, int out_size) {
    const float* x      = (const float*)d_in[0];
    const float* conv_w = (const float*)d_in[1];
    const float* conv_b = (const float*)d_in[2];
    const float* caps_w = (const float*)d_in[3];
    const float* caps_b = (const float*)d_in[4];
    const float* W      = (const float*)d_in[5];
    float* out = (float*)d_out;

    k_setup<<<1, 128>>>(W, caps_w, conv_b, caps_b);
    k_weff<<<128, 160>>>(caps_w, conv_w);
    k_xc<<<dim3(16, 8, 4), 128>>>(x);
    k_ucalc<<<dim3(16, 16), 128>>>();
    k_s0conv<<<dim3(16, 128), 128>>>();
    k_squash<<<1024, 256>>>(out);
}

// round 8
// speedup vs baseline: 2.3871x; 1.1909x over previous
#include <cuda_runtime.h>
#include <math.h>

// Shapes (fixed by the problem)
//  x       [16][16][4096]
//  conv_w  [256][16][9]
//  conv_b  [256]
//  caps_w  [8][16][256]
//  caps_b  [8][16]
//  W       [8][16][16]
//  out     [8][16][8][4096]  (n0, k, n, s)
//
// Algebra:
//  s0[n0,k,n,s] = Weff[n,k] (*) xc[n0,k] + beff           (xc = Σ_b C[n0,k,b]·x[b], ΣC=1)
//  U[k,n,s]     = Weff[n,k] (*) xU + 16·beff              (xU = Σ_b x[b])
//  s1 = s0·(1 + f0·s0·U); s2 = s0 + f1·s1²·U; out = f2·s2; f(SS)=√SS/(1+SS), SS=Σ_s s²

__device__ float g_C[128 * 16];          // [n0*16+k][b]
__device__ float g_Weff[128 * 144];      // [n*16+k][ic*9+dk]
__device__ float g_beff[128];            // [n*16+k]
__device__ float g_xc[128 * 16 * 4096];  // [n0*16+k][ic][s]   (32 MB)
__device__ float g_xU[16 * 4096];        // [ic][s]
__device__ float g_U[128 * 4096];        // [k*8+n][s]          (2 MB)
__device__ float g_s0[1024 * 4096];      // [n0*128+k*8+n][s]   (16 MB)

__device__ __forceinline__ void ffma2(unsigned long long& d,
                                      unsigned long long a,
                                      unsigned long long b) {
    asm("fma.rn.f32x2 %0, %1, %2, %0;" : "+l"(d) : "l"(a), "l"(b));
}

// ---------------------------------------------------------------------------
// K0: blocks 0..127 -> Weff rows; block 128 -> softmax(C) + beff
// ---------------------------------------------------------------------------
__global__ void k_init(const float* __restrict__ Wr,
                       const float* __restrict__ caps_w,
                       const float* __restrict__ conv_w,
                       const float* __restrict__ conv_b,
                       const float* __restrict__ caps_b) {
    if (blockIdx.x == 128) {
        int t = threadIdx.x;
        if (t < 128) {
            int n0 = t >> 4, k = t & 15;
            float m = -1e30f;
            float e[16];
            #pragma unroll
            for (int b = 0; b < 16; b++)
                m = fmaxf(m, Wr[(n0 * 16 + b) * 16 + k]);
            float sum = 0.f;
            #pragma unroll
            for (int b = 0; b < 16; b++) {
                float v = expf(Wr[(n0 * 16 + b) * 16 + k] - m);
                e[b] = v;
                sum += v;
            }
            float inv = 1.f / sum;
            #pragma unroll
            for (int b = 0; b < 16; b++)
                g_C[(n0 * 16 + k) * 16 + b] = e[b] * inv;

            float acc = caps_b[t];
            for (int oc = 0; oc < 256; oc++)
                acc += caps_w[t * 256 + oc] * conv_b[oc];
            g_beff[t] = acc;
        }
        return;
    }
    int nk = blockIdx.x;
    __shared__ float cw[256];
    for (int i = threadIdx.x; i < 256; i += blockDim.x)
        cw[i] = caps_w[nk * 256 + i];
    __syncthreads();
    int t = threadIdx.x;
    if (t < 144) {
        int ic = t / 9, dk = t - ic * 9;
        float acc = 0.f;
        for (int oc = 0; oc < 256; oc++)
            acc += cw[oc] * conv_w[(oc * 16 + ic) * 9 + dk];
        g_Weff[nk * 144 + t] = acc;
    }
}

// ---------------------------------------------------------------------------
// K1: xc[n0k][ic][s] = sum_b C[n0k][b]*x[b][ic][s];  xU[ic][s] = sum_b x
// grid (ic=16, stile=16 of 256); 128 thr, 2 s (float2) per thread, all 128 nk
// x read once (16 MB), xc write 32 MB.
// ---------------------------------------------------------------------------
__global__ __launch_bounds__(128) void k_xc(const float* __restrict__ x) {
    const int ic = blockIdx.x;
    const int sbase = blockIdx.y * 256;
    const int tid = threadIdx.x;

    __shared__ __align__(16) float xs[16][256];
    __shared__ float Cs[128][16];

    for (int idx = tid; idx < 16 * 64; idx += 128) {
        int b = idx >> 6, q = idx & 63;
        float4 v = *reinterpret_cast<const float4*>(&x[(b * 16 + ic) * 4096 + sbase + q * 4]);
        *reinterpret_cast<float4*>(&xs[b][q * 4]) = v;
    }
    for (int idx = tid; idx < 128 * 16; idx += 128)
        Cs[idx >> 4][idx & 15] = g_C[idx];
    __syncthreads();

    float xb[16][2];
    #pragma unroll
    for (int b = 0; b < 16; b++) {
        float2 v = *reinterpret_cast<const float2*>(&xs[b][tid * 2]);
        xb[b][0] = v.x; xb[b][1] = v.y;
    }

    {   // xU
        float u0 = 0.f, u1 = 0.f;
        #pragma unroll
        for (int b = 0; b < 16; b++) { u0 += xb[b][0]; u1 += xb[b][1]; }
        *reinterpret_cast<float2*>(&g_xU[ic * 4096 + sbase + tid * 2]) = make_float2(u0, u1);
    }

    for (int nk = 0; nk < 128; nk++) {
        float a0 = 0.f, a1 = 0.f;
        #pragma unroll
        for (int b = 0; b < 16; b++) {
            float c = Cs[nk][b];
            a0 = fmaf(c, xb[b][0], a0);
            a1 = fmaf(c, xb[b][1], a1);
        }
        *reinterpret_cast<float2*>(&g_xc[(nk * 16 + ic) * 4096 + sbase + tid * 2]) =
            make_float2(a0, a1);
    }
}

// ---------------------------------------------------------------------------
// K2: fused conv (s0 + U) with packed FFMA2.
// grid (stile=16 of 256, y=144): y<128 -> s0 block (n0k=y); y>=128 -> U block (k=y-128)
// block 128 thr: n = tid&7 (capsule), g = tid>>3 (s-subtile of 16)
// Parity-split accumulators:
//   A[j] (pair 2j,2j+1):  even taps dk=0,2,4,6,8 with E[j+dk/2]
//   B[j] (pair 2j-1,2j):  odd taps  dk=1,3,5,7   with E[j+(dk-1)/2]
//   E[j] = (x[sb+2j], x[sb+2j+1])  -- 8B-aligned LDS.64, no packing MOVs
//   out[2j] = A[j].lo + B[j].hi ;  out[2j+1] = A[j].hi + B[j+1].lo
// ---------------------------------------------------------------------------
__global__ __launch_bounds__(128) void k_conv() {
    const int sc = blockIdx.x * 256;
    const int y  = blockIdx.y;
    const bool isU = (y >= 128);
    const int k = isU ? (y - 128) : (y & 15);
    const int tid = threadIdx.x;
    const int n = tid & 7;
    const int g = tid >> 3;

    __shared__ __align__(16) float xt[16][264];
    __shared__ __align__(8) float2 ws2[8][145];   // (w,w) pairs, padded stride
    __shared__ float bs[8];

    const float* src = isU ? g_xU : &g_xc[(y * 16) * 4096];
    for (int j = tid; j < 16 * 264; j += 128) {
        int ic = j / 264, jj = j - ic * 264;
        int s = sc - 4 + jj;
        xt[ic][jj] = (s >= 0 && s < 4096) ? src[ic * 4096 + s] : 0.f;
    }
    for (int i = tid; i < 8 * 144; i += 128) {
        int n2 = i / 144, j = i - n2 * 144;
        float w = g_Weff[(n2 * 16 + k) * 144 + j];
        ws2[n2][j] = make_float2(w, w);
    }
    if (tid < 8) bs[tid] = g_beff[tid * 16 + k] * (isU ? 16.f : 1.f);
    __syncthreads();

    const float bv = bs[n];
    unsigned long long A[8], B[9];
    {
        float2 bp = make_float2(bv, bv);
        unsigned long long bu;
        __builtin_memcpy(&bu, &bp, 8);
        #pragma unroll
        for (int j = 0; j < 8; j++) A[j] = bu;
        #pragma unroll
        for (int j = 0; j < 9; j++) B[j] = 0ull;
    }

    const int sb = g * 16;
    const unsigned long long* wrow = reinterpret_cast<const unsigned long long*>(&ws2[n][0]);

    #pragma unroll
    for (int ic = 0; ic < 16; ic++) {
        unsigned long long E[12];
        #pragma unroll
        for (int j = 0; j < 12; j++)
            E[j] = *reinterpret_cast<const unsigned long long*>(&xt[ic][sb + 2 * j]);

        const unsigned long long* wp = wrow + ic * 9;
        // even taps
        #pragma unroll
        for (int e = 0; e < 5; e++) {
            unsigned long long w = wp[2 * e];
            #pragma unroll
            for (int j = 0; j < 8; j++) ffma2(A[j], w, E[j + e]);
        }
        // odd taps
        #pragma unroll
        for (int o = 0; o < 4; o++) {
            unsigned long long w = wp[2 * o + 1];
            #pragma unroll
            for (int j = 0; j < 9; j++) ffma2(B[j], w, E[j + o]);
        }
    }

    float2 a[8], b[9];
    #pragma unroll
    for (int j = 0; j < 8; j++) __builtin_memcpy(&a[j], &A[j], 8);
    #pragma unroll
    for (int j = 0; j < 9; j++) __builtin_memcpy(&b[j], &B[j], 8);

    float res[16];
    #pragma unroll
    for (int j = 0; j < 8; j++) {
        res[2 * j]     = a[j].x + b[j].y;
        res[2 * j + 1] = a[j].y + b[j + 1].x;
    }

    float* orow = isU ? &g_U[(k * 8 + n) * 4096 + sc]
                      : &g_s0[(((y >> 4) * 128) + k * 8 + n) * 4096 + sc];
    #pragma unroll
    for (int q = 0; q < 4; q++)
        *reinterpret_cast<float4*>(&orow[sb + q * 4]) =
            make_float4(res[q * 4], res[q * 4 + 1], res[q * 4 + 2], res[q * 4 + 3]);
}

// ---------------------------------------------------------------------------
// K3: squash iterations. one block per (n0,k,n) = bid; reads s0 row + U row.
// ---------------------------------------------------------------------------
__device__ __forceinline__ float block_reduce(float p, float* red, int tid) {
    #pragma unroll
    for (int o = 16; o > 0; o >>= 1)
        p += __shfl_xor_sync(0xffffffffu, p, o);
    __syncthreads();
    if ((tid & 31) == 0) red[tid >> 5] = p;
    __syncthreads();
    if (tid == 0) {
        float s = 0.f;
        #pragma unroll
        for (int i = 0; i < 8; i++) s += red[i];
        red[8] = s;
    }
    __syncthreads();
    return red[8];
}

__global__ __launch_bounds__(256) void k_squash(float* __restrict__ out) {
    const int bid = blockIdx.x;            // n0*128 + k*8 + n
    const int kn2 = bid & 127;             // k*8+n
    const int tid = threadIdx.x;

    __shared__ __align__(16) float s0s[4096];
    __shared__ __align__(16) float Us[4096];
    __shared__ float red[9];

    const float4* s0g = reinterpret_cast<const float4*>(&g_s0[bid * 4096]);
    const float4* Ug  = reinterpret_cast<const float4*>(&g_U[kn2 * 4096]);
    for (int i = tid; i < 1024; i += 256) {
        *reinterpret_cast<float4*>(&s0s[i * 4]) = s0g[i];
        *reinterpret_cast<float4*>(&Us[i * 4])  = Ug[i];
    }
    __syncthreads();

    float p, SS;

    p = 0.f;
    for (int s = tid; s < 4096; s += 256) { float v = s0s[s]; p = fmaf(v, v, p); }
    SS = block_reduce(p, red, tid);
    const float f0 = sqrtf(SS) / (1.f + SS);

    p = 0.f;
    for (int s = tid; s < 4096; s += 256) {
        float a = s0s[s], Uv = Us[s];
        float s1 = a * (1.f + f0 * a * Uv);
        p = fmaf(s1, s1, p);
    }
    SS = block_reduce(p, red, tid);
    const float f1 = sqrtf(SS) / (1.f + SS);

    p = 0.f;
    for (int s = tid; s < 4096; s += 256) {
        float a = s0s[s], Uv = Us[s];
        float s1 = a * (1.f + f0 * a * Uv);
        float s2 = a + f1 * s1 * s1 * Uv;
        p = fmaf(s2, s2, p);
    }
    SS = block_reduce(p, red, tid);
    const float f2 = sqrtf(SS) / (1.f + SS);

    float* orow = out + bid * 4096;
    for (int s = tid; s < 4096; s += 256) {
        float a = s0s[s], Uv = Us[s];
        float s1 = a * (1.f + f0 * a * Uv);
        float s2 = a + f1 * s1 * s1 * Uv;
        orow[s] = f2 * s2;
    }
}

// ---------------------------------------------------------------------------
extern "C" void kernel_launch(void* const* d_in, const int* in_sizes, int n_in,
                              void* d_out, int out_size) {
    const float* x      = (const float*)d_in[0];
    const float* conv_w = (const float*)d_in[1];
    const float* conv_b = (const float*)d_in[2];
    const float* caps_w = (const float*)d_in[3];
    const float* caps_b = (const float*)d_in[4];
    const float* W      = (const float*)d_in[5];
    float* out = (float*)d_out;

    k_init<<<129, 160>>>(W, caps_w, conv_w, conv_b, caps_b);
    k_xc<<<dim3(16, 16), 128>>>(x);
    k_conv<<<dim3(16, 144), 128>>>();
    k_squash<<<1024, 256>>>(out);
}

// round 9
// speedup vs baseline: 2.4710x; 1.0351x over previous
#include <cuda_runtime.h>
#include <math.h>

// Shapes (fixed by the problem)
//  x       [16][16][4096]
//  conv_w  [256][16][9]
//  conv_b  [256]
//  caps_w  [8][16][256]
//  caps_b  [8][16]
//  W       [8][16][16]
//  out     [8][16][8][4096]  (n0, k, n, s)
//
// Algebra:
//  s0[n0,k,n,s] = Weff[n,k] (*) xc[n0,k] + beff           (xc = Σ_b C[n0,k,b]·x[b], ΣC=1)
//  U[k,n,s]     = Weff[n,k] (*) xU + 16·beff              (xU = Σ_b x[b])
//  s1 = s0·(1 + f0·s0·U); s2 = s0 + f1·s1²·U; out = f2·s2; f(SS)=√SS/(1+SS), SS=Σ_s s²

__device__ float g_C[128 * 16];          // [n0*16+k][b]
__device__ float g_Weff[128 * 144];      // [n*16+k][ic*9+dk]
__device__ float g_beff[128];            // [n*16+k]
__device__ float g_xc[128 * 16 * 4096];  // [n0*16+k][ic][s]   (32 MB)
__device__ float g_xU[16 * 4096];        // [ic][s]
__device__ float g_U[128 * 4096];        // [k*8+n][s]          (2 MB)
__device__ float g_s0[1024 * 4096];      // [n0*128+k*8+n][s]   (16 MB)

__device__ __forceinline__ void ffma2(unsigned long long& d,
                                      unsigned long long a,
                                      unsigned long long b) {
    asm("fma.rn.f32x2 %0, %1, %2, %0;" : "+l"(d) : "l"(a), "l"(b));
}

// ---------------------------------------------------------------------------
// K0: blocks 0..127 -> Weff rows; block 128 -> softmax(C) + beff
// ---------------------------------------------------------------------------
__global__ void k_init(const float* __restrict__ Wr,
                       const float* __restrict__ caps_w,
                       const float* __restrict__ conv_w,
                       const float* __restrict__ conv_b,
                       const float* __restrict__ caps_b) {
    if (blockIdx.x == 128) {
        int t = threadIdx.x;
        if (t < 128) {
            int n0 = t >> 4, k = t & 15;
            float m = -1e30f;
            float e[16];
            #pragma unroll
            for (int b = 0; b < 16; b++)
                m = fmaxf(m, Wr[(n0 * 16 + b) * 16 + k]);
            float sum = 0.f;
            #pragma unroll
            for (int b = 0; b < 16; b++) {
                float v = expf(Wr[(n0 * 16 + b) * 16 + k] - m);
                e[b] = v;
                sum += v;
            }
            float inv = 1.f / sum;
            #pragma unroll
            for (int b = 0; b < 16; b++)
                g_C[(n0 * 16 + k) * 16 + b] = e[b] * inv;

            float acc = caps_b[t];
            for (int oc = 0; oc < 256; oc++)
                acc += caps_w[t * 256 + oc] * conv_b[oc];
            g_beff[t] = acc;
        }
        return;
    }
    int nk = blockIdx.x;
    __shared__ float cw[256];
    for (int i = threadIdx.x; i < 256; i += blockDim.x)
        cw[i] = caps_w[nk * 256 + i];
    __syncthreads();
    int t = threadIdx.x;
    if (t < 144) {
        int ic = t / 9, dk = t - ic * 9;
        float acc = 0.f;
        for (int oc = 0; oc < 256; oc++)
            acc += cw[oc] * conv_w[(oc * 16 + ic) * 9 + dk];
        g_Weff[nk * 144 + t] = acc;
    }
}

// ---------------------------------------------------------------------------
// K1: xc[n0k][ic][s] = sum_b C[n0k][b]*x[b][ic][s];  xU[ic][s] = sum_b x
// grid (ic=16, stile=8 of 512, nkhalf=2 of 64); 128 thr, 4 s (float4)/thread
// ---------------------------------------------------------------------------
__global__ __launch_bounds__(128) void k_xc(const float* __restrict__ x) {
    const int ic = blockIdx.x;
    const int sbase = blockIdx.y * 512;
    const int nk0 = blockIdx.z * 64;
    const int tid = threadIdx.x;

    __shared__ __align__(16) float xs[16][512];
    __shared__ float Cs[64][16];

    for (int idx = tid; idx < 16 * 128; idx += 128) {
        int b = idx >> 7, q = idx & 127;
        float4 v = *reinterpret_cast<const float4*>(&x[(b * 16 + ic) * 4096 + sbase + q * 4]);
        *reinterpret_cast<float4*>(&xs[b][q * 4]) = v;
    }
    for (int idx = tid; idx < 64 * 16; idx += 128)
        Cs[idx >> 4][idx & 15] = g_C[nk0 * 16 + idx];
    __syncthreads();

    float xb[16][4];
    #pragma unroll
    for (int b = 0; b < 16; b++) {
        float4 v = *reinterpret_cast<const float4*>(&xs[b][tid * 4]);
        xb[b][0] = v.x; xb[b][1] = v.y; xb[b][2] = v.z; xb[b][3] = v.w;
    }

    if (nk0 == 0) {  // xU once
        float u0 = 0.f, u1 = 0.f, u2 = 0.f, u3 = 0.f;
        #pragma unroll
        for (int b = 0; b < 16; b++) {
            u0 += xb[b][0]; u1 += xb[b][1]; u2 += xb[b][2]; u3 += xb[b][3];
        }
        *reinterpret_cast<float4*>(&g_xU[ic * 4096 + sbase + tid * 4]) =
            make_float4(u0, u1, u2, u3);
    }

    for (int j = 0; j < 64; j++) {
        float a0 = 0.f, a1 = 0.f, a2 = 0.f, a3 = 0.f;
        #pragma unroll
        for (int b = 0; b < 16; b++) {
            float c = Cs[j][b];
            a0 = fmaf(c, xb[b][0], a0);
            a1 = fmaf(c, xb[b][1], a1);
            a2 = fmaf(c, xb[b][2], a2);
            a3 = fmaf(c, xb[b][3], a3);
        }
        *reinterpret_cast<float4*>(&g_xc[((nk0 + j) * 16 + ic) * 4096 + sbase + tid * 4]) =
            make_float4(a0, a1, a2, a3);
    }
}

// ---------------------------------------------------------------------------
// K2: fused conv (s0 + U) with packed FFMA2 + skewed x tile.
// grid (stile=16 of 256, y=144): y<128 -> s0 block (n0k=y); y>=128 -> U (k=y-128)
// block 128 thr: n = tid&7 (capsule), g = tid>>3 (s-subtile of 16)
//
// Skewed tile: logical 16-float blocks stored at physical stride 18 floats.
//   phys(jj) = (jj>>4)*18 + (jj&15);  17 blocks cover 264 halo floats.
//   Warp g-lanes hit banks (g*18 mod 32) -> all distinct pairs: conflict-free.
// Parity-split FFMA2 accumulators as before:
//   A[j] pair(2j,2j+1) <- even taps; B[j] pair(2j-1,2j) <- odd taps
//   E[0..7] from block g (p0), E[8..11] from block g+1 (p1)
// ---------------------------------------------------------------------------
#define XT_ROW 306   // 17 blocks * 18 floats

__global__ __launch_bounds__(128) void k_conv() {
    const int sc = blockIdx.x * 256;
    const int y  = blockIdx.y;
    const bool isU = (y >= 128);
    const int k = isU ? (y - 128) : (y & 15);
    const int tid = threadIdx.x;
    const int n = tid & 7;
    const int g = tid >> 3;

    __shared__ __align__(16) float xt[16 * XT_ROW];
    __shared__ __align__(8) float2 ws2[8][145];   // (w,w) pairs, padded stride
    __shared__ float bs[8];

    const float* src = isU ? g_xU : &g_xc[(y * 16) * 4096];
    for (int j = tid; j < 16 * 264; j += 128) {
        int ic = j / 264, jj = j - ic * 264;
        int s = sc - 4 + jj;
        int phys = ((jj >> 4) * 18) + (jj & 15);
        xt[ic * XT_ROW + phys] = (s >= 0 && s < 4096) ? src[ic * 4096 + s] : 0.f;
    }
    for (int i = tid; i < 8 * 144; i += 128) {
        int n2 = i / 144, j = i - n2 * 144;
        float w = g_Weff[(n2 * 16 + k) * 144 + j];
        ws2[n2][j] = make_float2(w, w);
    }
    if (tid < 8) bs[tid] = g_beff[tid * 16 + k] * (isU ? 16.f : 1.f);
    __syncthreads();

    const float bv = bs[n];
    unsigned long long A[8], B[9];
    {
        float2 bp = make_float2(bv, bv);
        unsigned long long bu;
        __builtin_memcpy(&bu, &bp, 8);
        #pragma unroll
        for (int j = 0; j < 8; j++) A[j] = bu;
        #pragma unroll
        for (int j = 0; j < 9; j++) B[j] = 0ull;
    }

    const unsigned long long* wrow = reinterpret_cast<const unsigned long long*>(&ws2[n][0]);
    const int p0off = g * 18;            // block g
    const int p1off = (g + 1) * 18;      // block g+1

    #pragma unroll
    for (int ic = 0; ic < 16; ic++) {
        const float* row = &xt[ic * XT_ROW];
        unsigned long long E[12];
        #pragma unroll
        for (int j = 0; j < 8; j++)
            E[j] = *reinterpret_cast<const unsigned long long*>(row + p0off + 2 * j);
        #pragma unroll
        for (int m = 0; m < 4; m++)
            E[8 + m] = *reinterpret_cast<const unsigned long long*>(row + p1off + 2 * m);

        const unsigned long long* wp = wrow + ic * 9;
        #pragma unroll
        for (int e = 0; e < 5; e++) {
            unsigned long long w = wp[2 * e];
            #pragma unroll
            for (int j = 0; j < 8; j++) ffma2(A[j], w, E[j + e]);
        }
        #pragma unroll
        for (int o = 0; o < 4; o++) {
            unsigned long long w = wp[2 * o + 1];
            #pragma unroll
            for (int j = 0; j < 9; j++) ffma2(B[j], w, E[j + o]);
        }
    }

    float2 a[8], b[9];
    #pragma unroll
    for (int j = 0; j < 8; j++) __builtin_memcpy(&a[j], &A[j], 8);
    #pragma unroll
    for (int j = 0; j < 9; j++) __builtin_memcpy(&b[j], &B[j], 8);

    float res[16];
    #pragma unroll
    for (int j = 0; j < 8; j++) {
        res[2 * j]     = a[j].x + b[j].y;
        res[2 * j + 1] = a[j].y + b[j + 1].x;
    }

    const int sb = g * 16;
    float* orow = isU ? &g_U[(k * 8 + n) * 4096 + sc]
                      : &g_s0[(((y >> 4) * 128) + k * 8 + n) * 4096 + sc];
    #pragma unroll
    for (int q = 0; q < 4; q++)
        *reinterpret_cast<float4*>(&orow[sb + q * 4]) =
            make_float4(res[q * 4], res[q * 4 + 1], res[q * 4 + 2], res[q * 4 + 3]);
}

// ---------------------------------------------------------------------------
// K3: squash — register-resident. one block per (n0,k,n); thread holds 16 s.
// ---------------------------------------------------------------------------
__device__ __forceinline__ float block_reduce(float p, float* red, int tid) {
    #pragma unroll
    for (int o = 16; o > 0; o >>= 1)
        p += __shfl_xor_sync(0xffffffffu, p, o);
    __syncthreads();
    if ((tid & 31) == 0) red[tid >> 5] = p;
    __syncthreads();
    if (tid == 0) {
        float s = 0.f;
        #pragma unroll
        for (int i = 0; i < 8; i++) s += red[i];
        red[8] = s;
    }
    __syncthreads();
    return red[8];
}

__global__ __launch_bounds__(256) void k_squash(float* __restrict__ out) {
    const int bid = blockIdx.x;            // n0*128 + k*8 + n
    const int kn2 = bid & 127;             // k*8+n
    const int tid = threadIdx.x;

    __shared__ float red[9];

    float s0r[16], Ur[16];
    const float4* s0g = reinterpret_cast<const float4*>(&g_s0[bid * 4096]) + tid * 4;
    const float4* Ug  = reinterpret_cast<const float4*>(&g_U[kn2 * 4096]) + tid * 4;
    #pragma unroll
    for (int q = 0; q < 4; q++) {
        float4 v = s0g[q];
        s0r[q * 4 + 0] = v.x; s0r[q * 4 + 1] = v.y;
        s0r[q * 4 + 2] = v.z; s0r[q * 4 + 3] = v.w;
        float4 u = Ug[q];
        Ur[q * 4 + 0] = u.x; Ur[q * 4 + 1] = u.y;
        Ur[q * 4 + 2] = u.z; Ur[q * 4 + 3] = u.w;
    }

    float p, SS;

    p = 0.f;
    #pragma unroll
    for (int i = 0; i < 16; i++) p = fmaf(s0r[i], s0r[i], p);
    SS = block_reduce(p, red, tid);
    const float f0 = sqrtf(SS) / (1.f + SS);

    float s1r[16];
    p = 0.f;
    #pragma unroll
    for (int i = 0; i < 16; i++) {
        float s1 = s0r[i] * (1.f + f0 * s0r[i] * Ur[i]);
        s1r[i] = s1;
        p = fmaf(s1, s1, p);
    }
    SS = block_reduce(p, red, tid);
    const float f1 = sqrtf(SS) / (1.f + SS);

    float s2r[16];
    p = 0.f;
    #pragma unroll
    for (int i = 0; i < 16; i++) {
        float s2 = s0r[i] + f1 * s1r[i] * s1r[i] * Ur[i];
        s2r[i] = s2;
        p = fmaf(s2, s2, p);
    }
    SS = block_reduce(p, red, tid);
    const float f2 = sqrtf(SS) / (1.f + SS);

    float4* orow = reinterpret_cast<float4*>(out + bid * 4096) + tid * 4;
    #pragma unroll
    for (int q = 0; q < 4; q++)
        orow[q] = make_float4(f2 * s2r[q * 4], f2 * s2r[q * 4 + 1],
                              f2 * s2r[q * 4 + 2], f2 * s2r[q * 4 + 3]);
}

// ---------------------------------------------------------------------------
extern "C" void kernel_launch(void* const* d_in, const int* in_sizes, int n_in,
                              void* d_out, int out_size) {
    const float* x      = (const float*)d_in[0];
    const float* conv_w = (const float*)d_in[1];
    const float* conv_b = (const float*)d_in[2];
    const float* caps_w = (const float*)d_in[3];
    const float* caps_b = (const float*)d_in[4];
    const float* W      = (const float*)d_in[5];
    float* out = (float*)d_out;

    k_init<<<129, 160>>>(W, caps_w, conv_w, conv_b, caps_b);
    k_xc<<<dim3(16, 8, 2), 128>>>(x);
    k_conv<<<dim3(16, 144), 128>>>();
    k_squash<<<1024, 256>>>(out);
}

// round 13
// speedup vs baseline: 2.8039x; 1.1348x over previous
#include <cuda_runtime.h>
#include <math.h>

// Shapes (fixed by the problem)
//  x       [16][16][4096]
//  conv_w  [256][16][9]
//  conv_b  [256]
//  caps_w  [8][16][256]
//  caps_b  [8][16]
//  W       [8][16][16]
//  out     [8][16][8][4096]  (n0, k, n, s)
//
// Algebra:
//  s0[n0,k,n,s] = Weff[n,k] (*) xc[n0,k] + beff           (xc = Σ_b C[n0,k,b]·x[b], ΣC=1)
//  U[k,n,s]     = Weff[n,k] (*) xU + 16·beff              (xU = Σ_b x[b])
//  s1 = s0·(1 + f0·s0·U); s2 = s0 + f1·s1²·U; out = f2·s2; f(SS)=√SS/(1+SS), SS=Σ_s s²

__device__ float g_Weff[128 * 144];      // [n*16+k][ic*9+dk]
__device__ float g_beff[128];            // [n*16+k]
__device__ float g_xc[128 * 16 * 4096];  // [n0*16+k][ic][s]   (32 MB)
__device__ float g_xU[16 * 4096];        // [ic][s]
__device__ float g_U[128 * 4096];        // [k*8+n][s]          (2 MB)
__device__ float g_s0[1024 * 4096];      // [n0*128+k*8+n][s]   (16 MB)

__device__ __forceinline__ void ffma2(unsigned long long& d,
                                      unsigned long long a,
                                      unsigned long long b) {
    asm("fma.rn.f32x2 %0, %1, %2, %0;" : "+l"(d) : "l"(a), "l"(b));
}

// ---------------------------------------------------------------------------
// K0 (k_pre): blocks 0..127 -> xc/xU (with locally computed softmax C);
//             blocks 128..255 -> Weff rows; block 256 -> beff.
// ---------------------------------------------------------------------------
__global__ __launch_bounds__(160) void k_pre(const float* __restrict__ x,
                                             const float* __restrict__ Wr,
                                             const float* __restrict__ caps_w,
                                             const float* __restrict__ conv_w,
                                             const float* __restrict__ conv_b,
                                             const float* __restrict__ caps_b) {
    const int bx = blockIdx.x;
    const int tid = threadIdx.x;

    if (bx >= 128) {
        if (bx == 256) {
            if (tid < 128) {
                float acc = caps_b[tid];
                for (int oc = 0; oc < 256; oc++)
                    acc += caps_w[tid * 256 + oc] * conv_b[oc];
                g_beff[tid] = acc;
            }
            return;
        }
        // Weff row nk = bx-128
        int nk = bx - 128;
        __shared__ float cw[256];
        for (int i = tid; i < 256; i += 160)
            cw[i] = caps_w[nk * 256 + i];
        __syncthreads();
        if (tid < 144) {
            int ic = tid / 9, dk = tid - ic * 9;
            float acc = 0.f;
            for (int oc = 0; oc < 256; oc++)
                acc += cw[oc] * conv_w[(oc * 16 + ic) * 9 + dk];
            g_Weff[nk * 144 + tid] = acc;
        }
        return;
    }

    // --- xc block: ic = bx>>3, sbase = (bx&7)*512 ---
    const int ic = bx >> 3;
    const int sbase = (bx & 7) * 512;

    __shared__ __align__(16) float xs[16][512];
    __shared__ float Cs[128][16];

    // local softmax of W over b: thread t<128 handles (n0,k)=t
    if (tid < 128) {
        int n0 = tid >> 4, k = tid & 15;
        float m = -1e30f;
        float e[16];
        #pragma unroll
        for (int b = 0; b < 16; b++)
            m = fmaxf(m, Wr[(n0 * 16 + b) * 16 + k]);
        float sum = 0.f;
        #pragma unroll
        for (int b = 0; b < 16; b++) {
            float v = expf(Wr[(n0 * 16 + b) * 16 + k] - m);
            e[b] = v;
            sum += v;
        }
        float inv = 1.f / sum;
        #pragma unroll
        for (int b = 0; b < 16; b++)
            Cs[tid][b] = e[b] * inv;
    }
    for (int idx = tid; idx < 16 * 128; idx += 160) {
        int b = idx >> 7, q = idx & 127;
        float4 v = *reinterpret_cast<const float4*>(&x[(b * 16 + ic) * 4096 + sbase + q * 4]);
        *reinterpret_cast<float4*>(&xs[b][q * 4]) = v;
    }
    __syncthreads();

    if (tid >= 128) return;

    float xb[16][4];
    #pragma unroll
    for (int b = 0; b < 16; b++) {
        float4 v = *reinterpret_cast<const float4*>(&xs[b][tid * 4]);
        xb[b][0] = v.x; xb[b][1] = v.y; xb[b][2] = v.z; xb[b][3] = v.w;
    }

    {   // xU
        float u0 = 0.f, u1 = 0.f, u2 = 0.f, u3 = 0.f;
        #pragma unroll
        for (int b = 0; b < 16; b++) {
            u0 += xb[b][0]; u1 += xb[b][1]; u2 += xb[b][2]; u3 += xb[b][3];
        }
        *reinterpret_cast<float4*>(&g_xU[ic * 4096 + sbase + tid * 4]) =
            make_float4(u0, u1, u2, u3);
    }

    for (int nk = 0; nk < 128; nk++) {
        float a0 = 0.f, a1 = 0.f, a2 = 0.f, a3 = 0.f;
        #pragma unroll
        for (int b = 0; b < 16; b++) {
            float c = Cs[nk][b];
            a0 = fmaf(c, xb[b][0], a0);
            a1 = fmaf(c, xb[b][1], a1);
            a2 = fmaf(c, xb[b][2], a2);
            a3 = fmaf(c, xb[b][3], a3);
        }
        *reinterpret_cast<float4*>(&g_xc[(nk * 16 + ic) * 4096 + sbase + tid * 4]) =
            make_float4(a0, a1, a2, a3);
    }
}

// ---------------------------------------------------------------------------
// K1: fused conv (s0 + U) with packed FFMA2 + skewed x tile.
// grid (stile=16 of 256, y=144): y<128 -> s0 block (n0k=y); y>=128 -> U (k=y-128)
// block 128 thr: n = tid&7 (capsule), g = tid>>3 (s-subtile of 16)
// Skewed tile: logical 16-float blocks at physical stride 18 floats
//   -> warp g-lanes on distinct bank pairs, conflict-free LDS.64.
// Parity-split FFMA2: A[j] pair(2j,2j+1) even taps; B[j] pair(2j-1,2j) odd taps.
// ---------------------------------------------------------------------------
#define XT_ROW 306   // 17 blocks * 18 floats

__global__ __launch_bounds__(128) void k_conv() {
    const int sc = blockIdx.x * 256;
    const int y  = blockIdx.y;
    const bool isU = (y >= 128);
    const int k = isU ? (y - 128) : (y & 15);
    const int tid = threadIdx.x;
    const int n = tid & 7;
    const int g = tid >> 3;

    __shared__ __align__(16) float xt[16 * XT_ROW];
    __shared__ __align__(8) float2 ws2[8][145];
    __shared__ float bs[8];

    const float* src = isU ? g_xU : &g_xc[(y * 16) * 4096];
    for (int j = tid; j < 16 * 264; j += 128) {
        int ic = j / 264, jj = j - ic * 264;
        int s = sc - 4 + jj;
        int phys = ((jj >> 4) * 18) + (jj & 15);
        xt[ic * XT_ROW + phys] = (s >= 0 && s < 4096) ? src[ic * 4096 + s] : 0.f;
    }
    for (int i = tid; i < 8 * 144; i += 128) {
        int n2 = i / 144, j = i - n2 * 144;
        float w = g_Weff[(n2 * 16 + k) * 144 + j];
        ws2[n2][j] = make_float2(w, w);
    }
    if (tid < 8) bs[tid] = g_beff[tid * 16 + k] * (isU ? 16.f : 1.f);
    __syncthreads();

    const float bv = bs[n];
    unsigned long long A[8], B[9];
    {
        float2 bp = make_float2(bv, bv);
        unsigned long long bu;
        __builtin_memcpy(&bu, &bp, 8);
        #pragma unroll
        for (int j = 0; j < 8; j++) A[j] = bu;
        #pragma unroll
        for (int j = 0; j < 9; j++) B[j] = 0ull;
    }

    const unsigned long long* wrow = reinterpret_cast<const unsigned long long*>(&ws2[n][0]);
    const int p0off = g * 18;
    const int p1off = (g + 1) * 18;

    #pragma unroll
    for (int ic = 0; ic < 16; ic++) {
        const float* row = &xt[ic * XT_ROW];
        unsigned long long E[12];
        #pragma unroll
        for (int j = 0; j < 8; j++)
            E[j] = *reinterpret_cast<const unsigned long long*>(row + p0off + 2 * j);
        #pragma unroll
        for (int m = 0; m < 4; m++)
            E[8 + m] = *reinterpret_cast<const unsigned long long*>(row + p1off + 2 * m);

        const unsigned long long* wp = wrow + ic * 9;
        #pragma unroll
        for (int e = 0; e < 5; e++) {
            unsigned long long w = wp[2 * e];
            #pragma unroll
            for (int j = 0; j < 8; j++) ffma2(A[j], w, E[j + e]);
        }
        #pragma unroll
        for (int o = 0; o < 4; o++) {
            unsigned long long w = wp[2 * o + 1];
            #pragma unroll
            for (int j = 0; j < 9; j++) ffma2(B[j], w, E[j + o]);
        }
    }

    float2 a[8], b[9];
    #pragma unroll
    for (int j = 0; j < 8; j++) __builtin_memcpy(&a[j], &A[j], 8);
    #pragma unroll
    for (int j = 0; j < 9; j++) __builtin_memcpy(&b[j], &B[j], 8);

    float res[16];
    #pragma unroll
    for (int j = 0; j < 8; j++) {
        res[2 * j]     = a[j].x + b[j].y;
        res[2 * j + 1] = a[j].y + b[j + 1].x;
    }

    const int sb = g * 16;
    float* orow = isU ? &g_U[(k * 8 + n) * 4096 + sc]
                      : &g_s0[(((y >> 4) * 128) + k * 8 + n) * 4096 + sc];
    #pragma unroll
    for (int q = 0; q < 4; q++)
        *reinterpret_cast<float4*>(&orow[sb + q * 4]) =
            make_float4(res[q * 4], res[q * 4 + 1], res[q * 4 + 2], res[q * 4 + 3]);
}

// ---------------------------------------------------------------------------
// K2: squash — register-resident, COALESCED (thread holds s = {tid+q*1024}).
// ---------------------------------------------------------------------------
__device__ __forceinline__ float block_reduce(float p, float* red, int tid) {
    #pragma unroll
    for (int o = 16; o > 0; o >>= 1)
        p += __shfl_xor_sync(0xffffffffu, p, o);
    __syncthreads();
    if ((tid & 31) == 0) red[tid >> 5] = p;
    __syncthreads();
    if (tid == 0) {
        float s = 0.f;
        #pragma unroll
        for (int i = 0; i < 8; i++) s += red[i];
        red[8] = s;
    }
    __syncthreads();
    return red[8];
}

__global__ __launch_bounds__(256) void k_squash(float* __restrict__ out) {
    const int bid = blockIdx.x;            // n0*128 + k*8 + n
    const int kn2 = bid & 127;             // k*8+n
    const int tid = threadIdx.x;

    __shared__ float red[9];

    float s0r[16], Ur[16];
    const float4* s0g = reinterpret_cast<const float4*>(&g_s0[bid * 4096]);
    const float4* Ug  = reinterpret_cast<const float4*>(&g_U[kn2 * 4096]);
    #pragma unroll
    for (int q = 0; q < 4; q++) {
        float4 v = s0g[tid + q * 256];     // warp-coalesced: 32x16B contiguous
        s0r[q * 4 + 0] = v.x; s0r[q * 4 + 1] = v.y;
        s0r[q * 4 + 2] = v.z; s0r[q * 4 + 3] = v.w;
        float4 u = Ug[tid + q * 256];
        Ur[q * 4 + 0] = u.x; Ur[q * 4 + 1] = u.y;
        Ur[q * 4 + 2] = u.z; Ur[q * 4 + 3] = u.w;
    }

    float p, SS;

    p = 0.f;
    #pragma unroll
    for (int i = 0; i < 16; i++) p = fmaf(s0r[i], s0r[i], p);
    SS = block_reduce(p, red, tid);
    const float f0 = sqrtf(SS) / (1.f + SS);

    p = 0.f;
    #pragma unroll
    for (int i = 0; i < 16; i++) {
        float s1 = s0r[i] * (1.f + f0 * s0r[i] * Ur[i]);
        p = fmaf(s1, s1, p);
    }
    SS = block_reduce(p, red, tid);
    const float f1 = sqrtf(SS) / (1.f + SS);

    p = 0.f;
    #pragma unroll
    for (int i = 0; i < 16; i++) {
        float s1 = s0r[i] * (1.f + f0 * s0r[i] * Ur[i]);
        float s2 = s0r[i] + f1 * s1 * s1 * Ur[i];
        p = fmaf(s2, s2, p);
    }
    SS = block_reduce(p, red, tid);
    const float f2 = sqrtf(SS) / (1.f + SS);

    float4* orow = reinterpret_cast<float4*>(out + bid * 4096);
    #pragma unroll
    for (int q = 0; q < 4; q++) {
        float o[4];
        #pragma unroll
        for (int m = 0; m < 4; m++) {
            int i = q * 4 + m;
            float s1 = s0r[i] * (1.f + f0 * s0r[i] * Ur[i]);
            float s2 = s0r[i] + f1 * s1 * s1 * Ur[i];
            o[m] = f2 * s2;
        }
        orow[tid + q * 256] = make_float4(o[0], o[1], o[2], o[3]);
    }
}

// ---------------------------------------------------------------------------
extern "C" void kernel_launch(void* const* d_in, const int* in_sizes, int n_in,
                              void* d_out, int out_size) {
    const float* x      = (const float*)d_in[0];
    const float* conv_w = (const float*)d_in[1];
    const float* conv_b = (const float*)d_in[2];
    const float* caps_w = (const float*)d_in[3];
    const float* caps_b = (const float*)d_in[4];
    const float* W      = (const float*)d_in[5];
    float* out = (float*)d_out;

    k_pre<<<257, 160>>>(x, W, caps_w, conv_w, conv_b, caps_b);
    k_conv<<<dim3(16, 144), 128>>>();
    k_squash<<<1024, 256>>>(out);
}